// round 5
// baseline (speedup 1.0000x reference)
#include <cuda_runtime.h>
#include <stdint.h>

#define BATCH     128
#define SIG_SIZE  299592
#define HSIZE     37448          // levels 1..5, per batch
#define H4SIZE    4680           // levels 1..4, per batch
#define NOUT      51360          // Lyndon words, c=8, depth<=6
#define NBLK_LYN  76             // 4 + 8 + 64 tiles of 4096 words

// Scratch (static device memory only)
__device__ float g_H4[BATCH * H4SIZE];
__device__ float g_H5[BATCH * HSIZE];
__device__ int   g_jtab[NOUT];
__device__ int   g_blockcnt[NBLK_LYN];

__device__ __forceinline__ bool is_lyndon(unsigned w, int k) {
    #pragma unroll
    for (int r = 1; r < 6; r++) {
        if (r >= k) break;
        int sh = 3 * (k - r);
        unsigned rot = ((w & ((1u << sh) - 1u)) << (3 * r)) | (w >> sh);
        if (rot <= w) return false;
    }
    return true;
}

__device__ __forceinline__ void lyn_block_decode(int bb, int& level, int& tile) {
    if (bb < 4)       { level = bb + 1; tile = 0; }
    else if (bb < 12) { level = 5;      tile = bb - 4; }
    else              { level = 6;      tile = bb - 12; }
}

__device__ __forceinline__ int level_of(int e) {
    return (e < 8) ? 1 : (e < 72) ? 2 : (e < 584) ? 3 : (e < 4680) ? 4 : 5;
}

// ---------------------------------------------------------------------------
// K1: blocks [0,76): Lyndon per-block counts (256 thr x 16 words)
//     blocks [76,204): Horner steps 1..4 for batch b, fully in smem -> g_H4
// ---------------------------------------------------------------------------
__global__ void __launch_bounds__(256) k1_count_and_h4(const float* __restrict__ sig) {
    __shared__ float sA[H4SIZE];
    __shared__ float sB[H4SIZE];
    __shared__ int   sred[256];
    const int OFFL[7] = {0, 0, 8, 72, 584, 4680, 37448};
    int tid = threadIdx.x;

    if (blockIdx.x < NBLK_LYN) {
        int level, tile;
        lyn_block_decode(blockIdx.x, level, tile);
        int lsz  = 1 << (3 * level);
        int base = tile * 4096 + tid * 16;
        int cnt = 0;
        #pragma unroll
        for (int t = 0; t < 16; t++) {
            int w = base + t;
            if (w < lsz && is_lyndon((unsigned)w, level)) cnt++;
        }
        sred[tid] = cnt;
        __syncthreads();
        for (int o = 128; o > 0; o >>= 1) {
            if (tid < o) sred[tid] += sred[tid + o];
            __syncthreads();
        }
        if (tid == 0) g_blockcnt[blockIdx.x] = sred[0];
        return;
    }

    int b = blockIdx.x - NBLK_LYN;
    const float* xr = sig + (size_t)b * SIG_SIZE;
    const float C[5] = {0.f, -1.f/6.f, 1.f/5.f, -1.f/4.f, 1.f/3.f};

    // steps 1..4: dst = (s odd ? A : B), src = the other
    for (int s = 1; s <= 4; s++) {
        float c = C[s];
        float* dst = (s & 1) ? sA : sB;
        const float* src = (s & 1) ? sB : sA;
        int S = OFFL[s + 1];
        for (int e = tid; e < S; e += 256) {
            int k = level_of(e);
            int widx = e - OFFL[k];
            float v = __ldg(&xr[e]) * c;
            for (int i = 1; i < k; i++) {
                int sh = 3 * (k - i);
                v += __ldg(&xr[OFFL[i] + (widx >> sh)]) *
                     src[OFFL[k - i] + (widx & ((1 << sh) - 1))];
            }
            dst[e] = v;
        }
        __syncthreads();
    }
    // H4 is in sB (step 4 wrote B)
    float* h4 = g_H4 + (size_t)b * H4SIZE;
    for (int e = tid; e < H4SIZE; e += 256) h4[e] = sB[e];
}

// ---------------------------------------------------------------------------
// K2: blocks [0,76): Lyndon fill (each block computes its own prefix of the
//     76 counts — no separate scan kernel)
//     blocks [76, 76+128*147): Horner step 5: H5 = -1/2 x + x (x) H4 -> g_H5
// ---------------------------------------------------------------------------
#define H5_BLKS_PER_B 147   // ceil(37448/256)

__global__ void __launch_bounds__(256) k2_fill_and_h5(const float* __restrict__ sig) {
    const int OFFL[7] = {0, 0, 8, 72, 584, 4680, 37448};
    int tid = threadIdx.x;

    if (blockIdx.x < NBLK_LYN) {
        __shared__ int s[256];
        __shared__ int s_blockoff;
        int bb = blockIdx.x;
        int level, tile;
        lyn_block_decode(bb, level, tile);
        int lsz  = 1 << (3 * level);
        int base = tile * 4096 + tid * 16;
        int flags = 0, cnt = 0;
        #pragma unroll
        for (int t = 0; t < 16; t++) {
            int w = base + t;
            if (w < lsz && is_lyndon((unsigned)w, level)) { flags |= 1 << t; cnt++; }
        }
        s[tid] = cnt;
        if (tid == 0) {
            int acc = 0;
            for (int i = 0; i < bb; i++) acc += g_blockcnt[i];
            s_blockoff = acc;
        }
        __syncthreads();
        // Hillis-Steele inclusive scan over 256
        for (int off = 1; off < 256; off <<= 1) {
            int t = s[tid];
            if (tid >= off) t += s[tid - off];
            __syncthreads();
            s[tid] = t;
            __syncthreads();
        }
        int j = s_blockoff + (s[tid] - cnt);
        #pragma unroll
        for (int t = 0; t < 16; t++) {
            if ((flags >> t) & 1) g_jtab[j++] = (level << 20) | (base + t);
        }
        return;
    }

    int lin = blockIdx.x - NBLK_LYN;
    int b  = lin / H5_BLKS_PER_B;
    int eb = lin % H5_BLKS_PER_B;
    int e  = eb * 256 + tid;
    if (e >= HSIZE) return;

    const float* xr = sig  + (size_t)b * SIG_SIZE;
    const float* h4 = g_H4 + (size_t)b * H4SIZE;

    int k = level_of(e);
    int widx = e - OFFL[k];
    float v = __ldg(&xr[e]) * (-0.5f);
    for (int i = 1; i < k; i++) {
        int sh = 3 * (k - i);
        v += __ldg(&xr[OFFL[i] + (widx >> sh)]) *
             __ldg(&h4[OFFL[k - i] + (widx & ((1 << sh) - 1))]);
    }
    g_H5[(size_t)b * HSIZE + e] = v;
}

// ---------------------------------------------------------------------------
// K3: out[b][j] = (x (x) (1 + H5))[word(j)], fused Lyndon gather.
// First 584 floats of x and H5 staged in smem (levels 1..3).
// ---------------------------------------------------------------------------
__global__ void __launch_bounds__(256) k3_main(const float* __restrict__ sig,
                                              float* __restrict__ out) {
    __shared__ float sx[584];
    __shared__ float sh[584];
    const int OFFL[7] = {0, 0, 8, 72, 584, 4680, 37448};
    int b = blockIdx.y;
    const float* xr = sig  + (size_t)b * SIG_SIZE;
    const float* hr = g_H5 + (size_t)b * HSIZE;

    for (int i = threadIdx.x; i < 584; i += 256) {
        sx[i] = xr[i];
        sh[i] = hr[i];
    }
    __syncthreads();

    int j = blockIdx.x * 256 + threadIdx.x;
    if (j >= NOUT) return;

    int packed = __ldg(&g_jtab[j]);
    int k    = packed >> 20;
    int widx = packed & 0xFFFFF;

    float v;
    if (k == 6) {
        v  = __ldg(&xr[37448 + widx]);
        v += sx[       (widx >> 15)] * __ldg(&hr[4680 + (widx & 0x7FFF)]);
        v += sx[8   +  (widx >> 12)] * __ldg(&hr[584  + (widx & 0xFFF)]);
        v += sx[72  +  (widx >> 9) ] * sh[72 + (widx & 0x1FF)];
        v += __ldg(&xr[584  + (widx >> 6)]) * sh[8 + (widx & 0x3F)];
        v += __ldg(&xr[4680 + (widx >> 3)]) * sh[    (widx & 0x7)];
    } else {
        v = __ldg(&xr[OFFL[k] + widx]);
        for (int i = 1; i < k; i++) {
            int sh3 = 3 * (k - i);
            int po = OFFL[i]     + (widx >> sh3);
            int so = OFFL[k - i] + (widx & ((1 << sh3) - 1));
            float xp = (po < 584) ? sx[po] : __ldg(&xr[po]);
            float hs = (so < 584) ? sh[so] : __ldg(&hr[so]);
            v += xp * hs;
        }
    }
    out[(size_t)b * NOUT + j] = v;
}

// ---------------------------------------------------------------------------
extern "C" void kernel_launch(void* const* d_in, const int* in_sizes, int n_in,
                              void* d_out, int out_size) {
    (void)in_sizes; (void)n_in; (void)out_size;
    const float* sig = (const float*)d_in[0];
    float* out = (float*)d_out;

    // K1: Lyndon counts + Horner steps 1..4 (H4) in one launch
    k1_count_and_h4<<<NBLK_LYN + BATCH, 256>>>(sig);

    // K2: Lyndon fill + Horner step 5 (H5) in one launch
    k2_fill_and_h5<<<NBLK_LYN + BATCH * H5_BLKS_PER_B, 256>>>(sig);

    // K3: fused final product + Lyndon gather
    dim3 gm((NOUT + 255) / 256, BATCH);
    k3_main<<<gm, 256>>>(sig, out);
}

// round 6
// speedup vs baseline: 1.3789x; 1.3789x over previous
#include <cuda_runtime.h>
#include <stdint.h>

#define BATCH     128
#define SIG_SIZE  299592
#define HSIZE     37448          // levels 1..5, per batch
#define H4SIZE    4680           // levels 1..4, per batch
#define NOUT      51360          // Lyndon words, c=8, depth<=6
#define NBLK_LYN  76             // 4 + 8 + 64 tiles of 4096 words
#define H4CHUNKS  8              // level-4 split into 8 chunks of 512

// Scratch (static device memory only)
__device__ float g_H4[BATCH * H4SIZE];
__device__ float g_H5[BATCH * HSIZE];
__device__ int   g_jtab[NOUT];
__device__ int   g_blockcnt[NBLK_LYN];

__device__ __forceinline__ bool is_lyndon(unsigned w, int k) {
    #pragma unroll
    for (int r = 1; r < 6; r++) {
        if (r >= k) break;
        int sh = 3 * (k - r);
        unsigned rot = ((w & ((1u << sh) - 1u)) << (3 * r)) | (w >> sh);
        if (rot <= w) return false;
    }
    return true;
}

__device__ __forceinline__ void lyn_block_decode(int bb, int& level, int& tile) {
    if (bb < 4)       { level = bb + 1; tile = 0; }
    else if (bb < 12) { level = 5;      tile = bb - 4; }
    else              { level = 6;      tile = bb - 12; }
}

__device__ __forceinline__ int level_of(int e) {
    return (e < 8) ? 1 : (e < 72) ? 2 : (e < 584) ? 3 : (e < 4680) ? 4 : 5;
}

// Generic Horner entry: level-k entry widx of (c*x + x (x) src), src = prev H in smem.
__device__ __forceinline__ float horner_entry_smem(
        const float* __restrict__ xr, const float* __restrict__ src,
        int e, float c) {
    const int OFFL[7] = {0, 0, 8, 72, 584, 4680, 37448};
    int k = level_of(e);
    int widx = e - OFFL[k];
    float v = __ldg(&xr[e]) * c;
    for (int i = 1; i < k; i++) {
        int sh = 3 * (k - i);
        v += __ldg(&xr[OFFL[i] + (widx >> sh)]) *
             src[OFFL[k - i] + (widx & ((1 << sh) - 1))];
    }
    return v;
}

// ---------------------------------------------------------------------------
// K1: blocks [0,76): Lyndon per-block counts
//     blocks [76, 76+128*8): H4 build. Each block: levels 1..3 (584 entries,
//     redundant, in smem) then one 512-entry chunk of level 4 -> g_H4.
// ---------------------------------------------------------------------------
__global__ void __launch_bounds__(256) k1_count_and_h4(const float* __restrict__ sig) {
    __shared__ float sA[584];
    __shared__ float sB[584];
    __shared__ int   sred[256];
    int tid = threadIdx.x;

    if (blockIdx.x < NBLK_LYN) {
        int level, tile;
        lyn_block_decode(blockIdx.x, level, tile);
        int lsz  = 1 << (3 * level);
        int base = tile * 4096 + tid * 16;
        int cnt = 0;
        #pragma unroll
        for (int t = 0; t < 16; t++) {
            int w = base + t;
            if (w < lsz && is_lyndon((unsigned)w, level)) cnt++;
        }
        sred[tid] = cnt;
        __syncthreads();
        for (int o = 128; o > 0; o >>= 1) {
            if (tid < o) sred[tid] += sred[tid + o];
            __syncthreads();
        }
        if (tid == 0) g_blockcnt[blockIdx.x] = sred[0];
        return;
    }

    int lin   = blockIdx.x - NBLK_LYN;
    int b     = lin >> 3;
    int chunk = lin & (H4CHUNKS - 1);
    const float* xr = sig + (size_t)b * SIG_SIZE;
    float* h4 = g_H4 + (size_t)b * H4SIZE;

    // Step 1 -> sA (8 entries): H1 = -1/6 * x1
    if (tid < 8) sA[tid] = __ldg(&xr[tid]) * (-1.0f / 6.0f);
    __syncthreads();
    // Step 2 -> sB (72): H2 = 1/5*x + x(x)H1
    if (tid < 72) sB[tid] = horner_entry_smem(xr, sA, tid, 1.0f / 5.0f);
    __syncthreads();
    // Step 3 -> sA (584): H3 = -1/4*x + x(x)H2  (reads sB only; sA overwrite safe)
    for (int e = tid; e < 584; e += 256)
        sA[e] = horner_entry_smem(xr, sB, e, -1.0f / 4.0f);
    __syncthreads();
    // Step 4: H4 = 1/3*x + x(x)H3 (reads sA). chunk 0 also writes levels 1..3.
    if (chunk == 0) {
        for (int e = tid; e < 584; e += 256)
            h4[e] = horner_entry_smem(xr, sA, e, 1.0f / 3.0f);
    }
    int e0 = 584 + chunk * 512;
    for (int e = e0 + tid; e < e0 + 512; e += 256)
        h4[e] = horner_entry_smem(xr, sA, e, 1.0f / 3.0f);
}

// ---------------------------------------------------------------------------
// K2: blocks [0,76): Lyndon fill with PARALLEL prefix over the 76 counts
//     blocks [76, 76+128*147): Horner step 5: H5 = -1/2 x + x (x) H4 -> g_H5
// ---------------------------------------------------------------------------
#define H5_BLKS_PER_B 147   // ceil(37448/256)

__global__ void __launch_bounds__(256) k2_fill_and_h5(const float* __restrict__ sig) {
    const int OFFL[7] = {0, 0, 8, 72, 584, 4680, 37448};
    int tid = threadIdx.x;

    if (blockIdx.x < NBLK_LYN) {
        __shared__ int c76[128];
        __shared__ int s[256];
        int bb = blockIdx.x;
        int level, tile;
        lyn_block_decode(bb, level, tile);
        int lsz  = 1 << (3 * level);
        int base = tile * 4096 + tid * 16;
        int flags = 0, cnt = 0;
        #pragma unroll
        for (int t = 0; t < 16; t++) {
            int w = base + t;
            if (w < lsz && is_lyndon((unsigned)w, level)) { flags |= 1 << t; cnt++; }
        }
        s[tid] = cnt;
        // parallel load + inclusive scan of the 76 block counts (in 128 slots)
        if (tid < 128) c76[tid] = (tid < NBLK_LYN) ? g_blockcnt[tid] : 0;
        __syncthreads();
        for (int off = 1; off < 128; off <<= 1) {
            int t = 0;
            if (tid < 128) { t = c76[tid]; if (tid >= off) t += c76[tid - off]; }
            __syncthreads();
            if (tid < 128) c76[tid] = t;
            __syncthreads();
        }
        int blockoff = (bb == 0) ? 0 : c76[bb - 1];
        // inclusive scan of per-thread counts over 256 threads
        for (int off = 1; off < 256; off <<= 1) {
            int t = s[tid];
            if (tid >= off) t += s[tid - off];
            __syncthreads();
            s[tid] = t;
            __syncthreads();
        }
        int j = blockoff + (s[tid] - cnt);
        #pragma unroll
        for (int t = 0; t < 16; t++) {
            if ((flags >> t) & 1) g_jtab[j++] = (level << 20) | (base + t);
        }
        return;
    }

    int lin = blockIdx.x - NBLK_LYN;
    int b  = lin / H5_BLKS_PER_B;
    int eb = lin % H5_BLKS_PER_B;
    int e  = eb * 256 + tid;
    if (e >= HSIZE) return;

    const float* xr = sig  + (size_t)b * SIG_SIZE;
    const float* h4 = g_H4 + (size_t)b * H4SIZE;

    int k = level_of(e);
    int widx = e - OFFL[k];
    float v = __ldg(&xr[e]) * (-0.5f);
    for (int i = 1; i < k; i++) {
        int sh = 3 * (k - i);
        v += __ldg(&xr[OFFL[i] + (widx >> sh)]) *
             __ldg(&h4[OFFL[k - i] + (widx & ((1 << sh) - 1))]);
    }
    g_H5[(size_t)b * HSIZE + e] = v;
}

// ---------------------------------------------------------------------------
// K3: out[b][j] = (x (x) (1 + H5))[word(j)] — R3 known-good pure-__ldg form.
// ---------------------------------------------------------------------------
__global__ void __launch_bounds__(256) k3_main(const float* __restrict__ sig,
                                              float* __restrict__ out) {
    const int OFFL[7] = {0, 0, 8, 72, 584, 4680, 37448};
    int j = blockIdx.x * 256 + threadIdx.x;
    if (j >= NOUT) return;
    int b = blockIdx.y;

    int packed = __ldg(&g_jtab[j]);
    int k    = packed >> 20;
    int widx = packed & 0xFFFFF;

    const float* xr = sig  + (size_t)b * SIG_SIZE;
    const float* hr = g_H5 + (size_t)b * HSIZE;

    float v;
    if (k == 6) {
        v  = __ldg(&xr[37448 + widx]);
        v += __ldg(&xr[0    + (widx >> 15)]) * __ldg(&hr[4680 + (widx & 0x7FFF)]);
        v += __ldg(&xr[8    + (widx >> 12)]) * __ldg(&hr[584  + (widx & 0xFFF)]);
        v += __ldg(&xr[72   + (widx >> 9) ]) * __ldg(&hr[72   + (widx & 0x1FF)]);
        v += __ldg(&xr[584  + (widx >> 6) ]) * __ldg(&hr[8    + (widx & 0x3F)]);
        v += __ldg(&xr[4680 + (widx >> 3) ]) * __ldg(&hr[0    + (widx & 0x7)]);
    } else {
        v = __ldg(&xr[OFFL[k] + widx]);
        for (int i = 1; i < k; i++) {
            int sh = 3 * (k - i);
            v += __ldg(&xr[OFFL[i] + (widx >> sh)]) *
                 __ldg(&hr[OFFL[k - i] + (widx & ((1 << sh) - 1))]);
        }
    }
    out[(size_t)b * NOUT + j] = v;
}

// ---------------------------------------------------------------------------
extern "C" void kernel_launch(void* const* d_in, const int* in_sizes, int n_in,
                              void* d_out, int out_size) {
    (void)in_sizes; (void)n_in; (void)out_size;
    const float* sig = (const float*)d_in[0];
    float* out = (float*)d_out;

    // K1: Lyndon counts + H4 build (redundant low levels, chunked level 4)
    k1_count_and_h4<<<NBLK_LYN + BATCH * H4CHUNKS, 256>>>(sig);

    // K2: Lyndon fill (parallel prefix) + Horner step 5 (H5)
    k2_fill_and_h5<<<NBLK_LYN + BATCH * H5_BLKS_PER_B, 256>>>(sig);

    // K3: fused final product + Lyndon gather
    dim3 gm((NOUT + 255) / 256, BATCH);
    k3_main<<<gm, 256>>>(sig, out);
}